// round 4
// baseline (speedup 1.0000x reference)
#include <cuda_runtime.h>
#include <math.h>

// Problem constants
#define BATCH 16
#define CHAN  256
#define HDIM  96
#define HW    9216           // 96*96
#define SCALE 0.0625f        // 1/sqrt(256)

// Scratch for q,k,v: [3][B][C][HW] floats = 453 MB (device global: allocation-free)
__device__ float g_qkv[3ULL * BATCH * CHAN * HW];

// ---------------------------------------------------------------------------
// Kernel 1: fused QKV projection.
// For batch b:  Q = Wq @ X + bq, etc.  (M=256 per matrix, N=9216, K=256)
// Classic 128x128x8 smem-tiled SGEMM, 256 threads, 8x8 microtile.
// grid = (72, 6, 16): x = N tiles, y = stacked-M tiles (768/128), z = batch
// ---------------------------------------------------------------------------
#define BM 128
#define BN 128
#define BK 8

__global__ __launch_bounds__(256, 2)
void proj_kernel(const float* __restrict__ X,
                 const float* __restrict__ Wq, const float* __restrict__ bq,
                 const float* __restrict__ Wk, const float* __restrict__ bk,
                 const float* __restrict__ Wv, const float* __restrict__ bv)
{
    const int b     = blockIdx.z;
    const int tileM = blockIdx.y;            // 0..5
    const int mat   = tileM >> 1;            // 0=q, 1=k, 2=v
    const int mBase = (tileM & 1) * BM;      // 0 or 128 inside the matrix
    const int nBase = blockIdx.x * BN;

    const float* W    = (mat == 0) ? Wq : (mat == 1) ? Wk : Wv;
    const float* bias = (mat == 0) ? bq : (mat == 1) ? bk : bv;
    const float* Xb   = X + (size_t)b * CHAN * HW;

    __shared__ float As[BK][BM];
    __shared__ float Bs[BK][BN];

    const int tid = threadIdx.x;
    const int tx  = tid & 15;      // 0..15  -> n microtile
    const int ty  = tid >> 4;      // 0..15  -> m microtile

    // A-tile load mapping: 128 rows x 8 cols = 256 float4 (along k)
    const int aRow  = tid >> 1;          // 0..127
    const int aCol4 = (tid & 1) * 4;     // 0 or 4
    // B-tile load mapping: 8 rows x 128 cols = 256 float4 (along n)
    const int bRow  = tid >> 5;          // 0..7
    const int bCol  = (tid & 31) * 4;    // 0..124

    float acc[8][8];
#pragma unroll
    for (int i = 0; i < 8; i++)
#pragma unroll
        for (int j = 0; j < 8; j++) acc[i][j] = 0.0f;

    for (int k0 = 0; k0 < CHAN; k0 += BK) {
        float4 av = *(const float4*)&W[(size_t)(mBase + aRow) * CHAN + k0 + aCol4];
        As[aCol4 + 0][aRow] = av.x;
        As[aCol4 + 1][aRow] = av.y;
        As[aCol4 + 2][aRow] = av.z;
        As[aCol4 + 3][aRow] = av.w;
        *(float4*)&Bs[bRow][bCol] =
            *(const float4*)&Xb[(size_t)(k0 + bRow) * HW + nBase + bCol];
        __syncthreads();

#pragma unroll
        for (int kk = 0; kk < BK; kk++) {
            float a[8], bb[8];
            *(float4*)&a[0]  = *(float4*)&As[kk][ty * 8];
            *(float4*)&a[4]  = *(float4*)&As[kk][ty * 8 + 4];
            *(float4*)&bb[0] = *(float4*)&Bs[kk][tx * 8];
            *(float4*)&bb[4] = *(float4*)&Bs[kk][tx * 8 + 4];
#pragma unroll
            for (int i = 0; i < 8; i++)
#pragma unroll
                for (int j = 0; j < 8; j++)
                    acc[i][j] = fmaf(a[i], bb[j], acc[i][j]);
        }
        __syncthreads();
    }

    // Store to scratch: g_qkv[mat][b][d][s]
    float* outBase = g_qkv + ((size_t)mat * BATCH + b) * CHAN * HW;
#pragma unroll
    for (int i = 0; i < 8; i++) {
        const int d  = mBase + ty * 8 + i;
        const float bv = bias[d];
        size_t off = (size_t)d * HW + nBase + tx * 8;
        float4 v0 = { acc[i][0] + bv, acc[i][1] + bv, acc[i][2] + bv, acc[i][3] + bv };
        float4 v1 = { acc[i][4] + bv, acc[i][5] + bv, acc[i][6] + bv, acc[i][7] + bv };
        *(float4*)&outBase[off]     = v0;
        *(float4*)&outBase[off + 4] = v1;
    }
}

// ---------------------------------------------------------------------------
// Kernel 2: per-(b,c) attention plane.
// scores = (q @ k^T) * SCALE ; softmax rows ; attended = weights @ v ; +fmap
// One block per (b,c): 256 threads, 6x6 microtile over 96x96, smem pitch 97.
// Dynamic smem: 3 * 96 * 97 * 4 = 111744 bytes  (q|v buffer, k buffer, scores)
// ---------------------------------------------------------------------------
#define PIT 97
#define ATTN_SMEM (3 * HDIM * PIT * 4)

__global__ __launch_bounds__(256)
void attn_kernel(const float* __restrict__ fmap, float* __restrict__ out)
{
    extern __shared__ float sm[];
    float* qs = sm;                   // later reused for v
    float* ks = sm + HDIM * PIT;
    float* sc = sm + 2 * HDIM * PIT;

    const int bc = blockIdx.x;        // b*256 + c
    const size_t plane    = (size_t)bc * HW;
    const size_t matStride = (size_t)BATCH * CHAN * HW;
    const float* qg = g_qkv + plane;
    const float* kg = g_qkv + matStride + plane;
    const float* vg = g_qkv + 2 * matStride + plane;

    const int tid = threadIdx.x;

    // Load q and k planes into smem (pitch 97)
    for (int i = tid; i < HW; i += 256) {
        int h = i / HDIM, w = i - h * HDIM;
        qs[h * PIT + w] = qg[i];
        ks[h * PIT + w] = kg[i];
    }
    __syncthreads();

    const int tx = tid & 15;          // g / w microtile
    const int ty = tid >> 4;          // h microtile
    const int h0 = ty * 6;
    const int g0 = tx * 6;

    // Phase 1: scores = q @ k^T * SCALE
    {
        float acc[6][6];
#pragma unroll
        for (int i = 0; i < 6; i++)
#pragma unroll
            for (int j = 0; j < 6; j++) acc[i][j] = 0.0f;

        for (int w = 0; w < HDIM; w++) {
            float a[6], bb[6];
#pragma unroll
            for (int j = 0; j < 6; j++) a[j]  = qs[(h0 + j) * PIT + w];
#pragma unroll
            for (int j = 0; j < 6; j++) bb[j] = ks[(g0 + j) * PIT + w];
#pragma unroll
            for (int i = 0; i < 6; i++)
#pragma unroll
                for (int j = 0; j < 6; j++)
                    acc[i][j] = fmaf(a[i], bb[j], acc[i][j]);
        }
#pragma unroll
        for (int i = 0; i < 6; i++)
#pragma unroll
            for (int j = 0; j < 6; j++)
                sc[(h0 + i) * PIT + g0 + j] = acc[i][j] * SCALE;
    }
    __syncthreads();

    // Phase 2: row softmax (8 warps x 12 rows each)
    {
        const int warp = tid >> 5, lane = tid & 31;
        for (int r = warp; r < HDIM; r += 8) {
            float m = -1e30f;
            for (int j = lane; j < HDIM; j += 32) m = fmaxf(m, sc[r * PIT + j]);
#pragma unroll
            for (int o = 16; o; o >>= 1) m = fmaxf(m, __shfl_xor_sync(0xffffffffu, m, o));
            float e[3]; float s = 0.0f;
            {
                int t = 0;
                for (int j = lane; j < HDIM; j += 32, t++) {
                    e[t] = __expf(sc[r * PIT + j] - m);
                    s += e[t];
                }
            }
#pragma unroll
            for (int o = 16; o; o >>= 1) s += __shfl_xor_sync(0xffffffffu, s, o);
            const float inv = 1.0f / s;
            {
                int t = 0;
                for (int j = lane; j < HDIM; j += 32, t++)
                    sc[r * PIT + j] = e[t] * inv;
            }
        }
    }
    __syncthreads();

    // Load v into the q buffer
    for (int i = tid; i < HW; i += 256) {
        int h = i / HDIM, w = i - h * HDIM;
        qs[h * PIT + w] = vg[i];
    }
    __syncthreads();

    // Phase 3: attended = weights @ v ; out = fmap + attended
    {
        float acc[6][6];
#pragma unroll
        for (int i = 0; i < 6; i++)
#pragma unroll
            for (int j = 0; j < 6; j++) acc[i][j] = 0.0f;

        const int w0 = g0;  // tx*6 now indexes w
        for (int g = 0; g < HDIM; g++) {
            float a[6], bb[6];
#pragma unroll
            for (int j = 0; j < 6; j++) a[j]  = sc[(h0 + j) * PIT + g];
#pragma unroll
            for (int j = 0; j < 6; j++) bb[j] = qs[g * PIT + w0 + j];
#pragma unroll
            for (int i = 0; i < 6; i++)
#pragma unroll
                for (int j = 0; j < 6; j++)
                    acc[i][j] = fmaf(a[i], bb[j], acc[i][j]);
        }

        const float* fm = fmap + plane;
        float* og = out + plane;
#pragma unroll
        for (int i = 0; i < 6; i++)
#pragma unroll
            for (int j = 0; j < 6; j++) {
                int idx = (h0 + i) * HDIM + w0 + j;
                og[idx] = fm[idx] + acc[i][j];
            }
    }
}

// ---------------------------------------------------------------------------
// Launch
// Inputs (metadata order): feature, feature_map, Wq, bq, Wk, bk, Wv, bv
// ---------------------------------------------------------------------------
extern "C" void kernel_launch(void* const* d_in, const int* in_sizes, int n_in,
                              void* d_out, int out_size)
{
    const float* feature  = (const float*)d_in[0];
    const float* fmap     = (const float*)d_in[1];
    const float* Wq       = (const float*)d_in[2];
    const float* bq       = (const float*)d_in[3];
    const float* Wk       = (const float*)d_in[4];
    const float* bk       = (const float*)d_in[5];
    const float* Wv       = (const float*)d_in[6];
    const float* bv       = (const float*)d_in[7];
    float* out            = (float*)d_out;

    // Attention kernel needs 111744 B of dynamic smem (> 48 KB default).
    // Idempotent host-side call; executes immediately, not captured.
    cudaFuncSetAttribute(attn_kernel,
                         cudaFuncAttributeMaxDynamicSharedMemorySize,
                         ATTN_SMEM);

    dim3 g1(HW / BN, 6, BATCH);   // (72, 6, 16)
    proj_kernel<<<g1, 256>>>(feature, Wq, bq, Wk, bk, Wv, bv);

    attn_kernel<<<BATCH * CHAN, 256, ATTN_SMEM>>>(fmap, out);
}